// round 1
// baseline (speedup 1.0000x reference)
#include <cuda_runtime.h>
#include <math.h>

#define NN 100000
#define EE 1600000
#define GG 2048
#define NCOUT 204

// ---------------- static scratch (no runtime allocation allowed) ----------------
__device__ float g_bufA[NN * 128];       // t (GEMM input) per layer
__device__ float g_bufB[NN * 128];       // y (pre-BN GEMM output) per layer
__device__ int   g_rowptr[NN + 1];
__device__ int   g_cursor[NN];
__device__ int   g_col[EE];
__device__ float g_stats[1024];          // [sum(0..C) | sumsq(C..2C)]
__device__ float g_scale[512];
__device__ float g_shift[512];
__device__ float g_xg[GG * 128];
__device__ float g_m1[GG * 512];
__device__ float g_m2[GG * 256];

// ---------------- CSR build ----------------
__global__ void hist_kernel(const int* __restrict__ edst) {
    int e = blockIdx.x * blockDim.x + threadIdx.x;
    if (e < EE) atomicAdd(&g_rowptr[edst[e] + 1], 1);
}

__global__ void scan_kernel(int* a, int n) {
    __shared__ int s[1024];
    __shared__ int carry;
    if (threadIdx.x == 0) carry = 0;
    __syncthreads();
    for (int base = 0; base < n; base += 1024) {
        int i = base + threadIdx.x;
        int v = (i < n) ? a[i] : 0;
        s[threadIdx.x] = v;
        __syncthreads();
        for (int off = 1; off < 1024; off <<= 1) {
            int t = (threadIdx.x >= off) ? s[threadIdx.x - off] : 0;
            __syncthreads();
            s[threadIdx.x] += t;
            __syncthreads();
        }
        int total = s[1023];
        if (i < n) a[i] = s[threadIdx.x] + carry;
        __syncthreads();
        if (threadIdx.x == 0) carry += total;
        __syncthreads();
    }
}

__global__ void fill_kernel(const int* __restrict__ esrc, const int* __restrict__ edst) {
    int e = blockIdx.x * blockDim.x + threadIdx.x;
    if (e >= EE) return;
    int d = edst[e];
    int pos = atomicAdd(&g_cursor[d], 1);
    g_col[g_rowptr[d] + pos] = esrc[e];
}

// ---------------- layer 0 aggregation: t = 2*h + sum_in(h), 78 dims ----------------
__global__ void agg0_kernel(const float* __restrict__ H) {
    int w = (blockIdx.x * blockDim.x + threadIdx.x) >> 5;
    if (w >= NN) return;
    int lid = threadIdx.x & 31;
    const float* hr = H + (size_t)w * 78;
    float a0 = 2.f * hr[lid];
    float a1 = 2.f * hr[lid + 32];
    float a2 = (lid < 14) ? 2.f * hr[lid + 64] : 0.f;
    int beg = g_rowptr[w], end = g_rowptr[w + 1];
    for (int j = beg; j < end; ++j) {
        int s = g_col[j];
        const float* hs = H + (size_t)s * 78;
        a0 += hs[lid];
        a1 += hs[lid + 32];
        if (lid < 14) a2 += hs[lid + 64];
    }
    float* t = g_bufA + (size_t)w * 128;
    t[lid] = a0;
    t[lid + 32] = a1;
    if (lid < 14) t[lid + 64] = a2;
}

// ---------------- mid-layer aggregation (128 dims), BN+ReLU fused on the read side --------
// x = relu(y*scale + shift);  t[n] = 2*x[n] + sum_{src in CSR[n]} x[src]
__global__ void agg_kernel(const float* __restrict__ Yin, float* __restrict__ Tout,
                           const float* __restrict__ scale, const float* __restrict__ shift) {
    int w = (blockIdx.x * blockDim.x + threadIdx.x) >> 5;
    if (w >= NN) return;
    int lid = threadIdx.x & 31;
    float4 sc = *(const float4*)&scale[lid * 4];
    float4 sh = *(const float4*)&shift[lid * 4];
    const float4* Y4 = (const float4*)Yin;
    float4 v = Y4[(size_t)w * 32 + lid];
    float a0 = 2.f * fmaxf(0.f, v.x * sc.x + sh.x);
    float a1 = 2.f * fmaxf(0.f, v.y * sc.y + sh.y);
    float a2 = 2.f * fmaxf(0.f, v.z * sc.z + sh.z);
    float a3 = 2.f * fmaxf(0.f, v.w * sc.w + sh.w);
    int beg = g_rowptr[w], end = g_rowptr[w + 1];
    for (int j = beg; j < end; ++j) {
        int s = g_col[j];
        float4 u = Y4[(size_t)s * 32 + lid];
        a0 += fmaxf(0.f, u.x * sc.x + sh.x);
        a1 += fmaxf(0.f, u.y * sc.y + sh.y);
        a2 += fmaxf(0.f, u.z * sc.z + sh.z);
        a3 += fmaxf(0.f, u.w * sc.w + sh.w);
    }
    float4 o = make_float4(a0, a1, a2, a3);
    ((float4*)Tout)[(size_t)w * 32 + lid] = o;
}

// ---------------- readout: xg[graph] += relu(bn(y[n])) ----------------
__global__ void readout_kernel(const float* __restrict__ Yin, const int* __restrict__ gid,
                               const float* __restrict__ scale, const float* __restrict__ shift) {
    int w = (blockIdx.x * blockDim.x + threadIdx.x) >> 5;
    if (w >= NN) return;
    int lid = threadIdx.x & 31;
    float4 sc = *(const float4*)&scale[lid * 4];
    float4 sh = *(const float4*)&shift[lid * 4];
    float4 v = ((const float4*)Yin)[(size_t)w * 32 + lid];
    int g = gid[w];
    float* dst = &g_xg[(size_t)g * 128 + lid * 4];
    atomicAdd(dst + 0, fmaxf(0.f, v.x * sc.x + sh.x));
    atomicAdd(dst + 1, fmaxf(0.f, v.y * sc.y + sh.y));
    atomicAdd(dst + 2, fmaxf(0.f, v.z * sc.z + sh.z));
    atomicAdd(dst + 3, fmaxf(0.f, v.w * sc.w + sh.w));
}

// ---------------- GEMM: Y[rows,128] = T[rows,128(K valid)] @ W[K,128] + bscale*bias ------
// Fused per-column sum/sumsq accumulation for BN stats.
__global__ void __launch_bounds__(256) gemm128_kernel(
    const float* __restrict__ T, const float* __restrict__ W,
    const float* __restrict__ bias, float bscale, int rows, int K,
    float* __restrict__ Y, float* __restrict__ stats) {
    extern __shared__ float sm[];
    float* Ws = sm;              // 128*128
    float* Ts = sm + 128 * 128;  // 64*128
    int tid = threadIdx.x;
    for (int idx = tid; idx < 128 * 128; idx += 256) {
        int k = idx >> 7, c = idx & 127;
        Ws[idx] = (k < K) ? W[k * 128 + c] : 0.f;
    }
    int row0 = blockIdx.x * 64;
    for (int idx = tid; idx < 64 * 128; idx += 256) {
        int r = idx >> 7, k = idx & 127;
        int gr = row0 + r;
        Ts[idx] = (gr < rows && k < K) ? T[(size_t)gr * 128 + k] : 0.f;
    }
    __syncthreads();
    int tx = tid & 31, ty = tid >> 5;
    float acc[8][4];
#pragma unroll
    for (int i = 0; i < 8; i++)
#pragma unroll
        for (int j = 0; j < 4; j++) acc[i][j] = 0.f;

    for (int k = 0; k < 128; k += 4) {
        float4 w0 = *(const float4*)&Ws[(k + 0) * 128 + tx * 4];
        float4 w1 = *(const float4*)&Ws[(k + 1) * 128 + tx * 4];
        float4 w2 = *(const float4*)&Ws[(k + 2) * 128 + tx * 4];
        float4 w3 = *(const float4*)&Ws[(k + 3) * 128 + tx * 4];
#pragma unroll
        for (int i = 0; i < 8; i++) {
            float4 t4 = *(const float4*)&Ts[(ty + i * 8) * 128 + k];
            acc[i][0] = fmaf(t4.x, w0.x, fmaf(t4.y, w1.x, fmaf(t4.z, w2.x, fmaf(t4.w, w3.x, acc[i][0]))));
            acc[i][1] = fmaf(t4.x, w0.y, fmaf(t4.y, w1.y, fmaf(t4.z, w2.y, fmaf(t4.w, w3.y, acc[i][1]))));
            acc[i][2] = fmaf(t4.x, w0.z, fmaf(t4.y, w1.z, fmaf(t4.z, w2.z, fmaf(t4.w, w3.z, acc[i][2]))));
            acc[i][3] = fmaf(t4.x, w0.w, fmaf(t4.y, w1.w, fmaf(t4.z, w2.w, fmaf(t4.w, w3.w, acc[i][3]))));
        }
    }

    float4 bv = *(const float4*)&bias[tx * 4];
    float csum[4] = {0, 0, 0, 0}, csq[4] = {0, 0, 0, 0};
#pragma unroll
    for (int i = 0; i < 8; i++) {
        int gr = row0 + ty + i * 8;
        if (gr < rows) {
            float v0 = acc[i][0] + bscale * bv.x;
            float v1 = acc[i][1] + bscale * bv.y;
            float v2 = acc[i][2] + bscale * bv.z;
            float v3 = acc[i][3] + bscale * bv.w;
            float4 o = make_float4(v0, v1, v2, v3);
            *(float4*)&Y[(size_t)gr * 128 + tx * 4] = o;
            csum[0] += v0; csq[0] += v0 * v0;
            csum[1] += v1; csq[1] += v1 * v1;
            csum[2] += v2; csq[2] += v2 * v2;
            csum[3] += v3; csq[3] += v3 * v3;
        }
    }
    __syncthreads();
    float* ss = sm;  // reuse: 256 floats (sum[128] | sumsq[128])
    ss[tid] = 0.f;
    __syncthreads();
#pragma unroll
    for (int j = 0; j < 4; j++) {
        atomicAdd(&ss[tx * 4 + j], csum[j]);
        atomicAdd(&ss[128 + tx * 4 + j], csq[j]);
    }
    __syncthreads();
    if (tid < 128) {
        atomicAdd(&stats[tid], ss[tid]);
        atomicAdd(&stats[128 + tid], ss[128 + tid]);
    }
}

// ---------------- BN coefficient finalize ----------------
__global__ void finalize_kernel(const float* __restrict__ stats, const float* __restrict__ gamma,
                                const float* __restrict__ beta, float invn, int C,
                                float* __restrict__ scale, float* __restrict__ shift) {
    int c = blockIdx.x * blockDim.x + threadIdx.x;
    if (c >= C) return;
    float mu = stats[c] * invn;
    float var = stats[C + c] * invn - mu * mu;
    float inv = rsqrtf(var + 1e-5f);
    float s = gamma[c] * inv;
    scale[c] = s;
    shift[c] = beta[c] - mu * s;
}

// ---------------- small MLP GEMM (thread-per-output) ----------------
__global__ void gemm_small_kernel(const float* __restrict__ X, const float* __restrict__ W,
                                  const float* __restrict__ bias, int R, int K, int C,
                                  float* __restrict__ Y, float* __restrict__ stats) {
    int c = blockIdx.x * 32 + (threadIdx.x & 31);
    int r = blockIdx.y * 8 + (threadIdx.x >> 5);
    if (c >= C || r >= R) return;
    float acc = bias[c];
    const float* xr = X + (size_t)r * K;
    for (int k = 0; k < K; ++k) acc = fmaf(xr[k], W[(size_t)k * C + c], acc);
    Y[(size_t)r * C + c] = acc;
    atomicAdd(&stats[c], acc);
    atomicAdd(&stats[C + c], acc * acc);
}

__global__ void norm_relu_kernel(float* __restrict__ Y, const float* __restrict__ scale,
                                 const float* __restrict__ shift, int total, int C) {
    int i = blockIdx.x * blockDim.x + threadIdx.x;
    if (i >= total) return;
    int c = i % C;
    float v = Y[i] * scale[c] + shift[c];
    Y[i] = fmaxf(v, 0.f);
}

__global__ void fc2_kernel(const float* __restrict__ X, const float* __restrict__ W,
                           const float* __restrict__ bias, float* __restrict__ out) {
    int c = blockIdx.x * 32 + (threadIdx.x & 31);
    int g = blockIdx.y * 8 + (threadIdx.x >> 5);
    if (c >= NCOUT || g >= GG) return;
    float acc = bias[204 + c];
    const float* xr = X + (size_t)g * 256;
    for (int k = 0; k < 256; ++k) acc = fmaf(xr[k], W[(size_t)k * 408 + 204 + c], acc);
    out[(size_t)g * NCOUT + c] = 1.f / (1.f + expf(-acc));
}

// ---------------- host orchestration ----------------
extern "C" void kernel_launch(void* const* d_in, const int* in_sizes, int n_in,
                              void* d_out, int out_size) {
    const float* h        = (const float*)d_in[0];
    const int*   esrc     = (const int*)d_in[1];
    const int*   edst     = (const int*)d_in[2];
    const int*   gid      = (const int*)d_in[3];
    const float* W1       = (const float*)d_in[4];
    const float* b1       = (const float*)d_in[5];
    const float* g1_gamma = (const float*)d_in[6];
    const float* g1_beta  = (const float*)d_in[7];
    const float* Wg       = (const float*)d_in[8];
    const float* bg       = (const float*)d_in[9];
    const float* gg       = (const float*)d_in[10];
    const float* gb       = (const float*)d_in[11];
    const float* fc1_W    = (const float*)d_in[12];
    const float* fc1_b    = (const float*)d_in[13];
    const float* bn1_g    = (const float*)d_in[14];
    const float* bn1_b    = (const float*)d_in[15];
    const float* lin_W    = (const float*)d_in[16];
    const float* lin_b    = (const float*)d_in[17];
    const float* lbn_g    = (const float*)d_in[18];
    const float* lbn_b    = (const float*)d_in[19];
    const float* fc2_W    = (const float*)d_in[20];
    const float* fc2_b    = (const float*)d_in[21];
    float* out = (float*)d_out;

    float *bufA, *bufB, *stats, *scalep, *shiftp, *xg, *m1, *m2;
    int *rowptr, *cursor;
    cudaGetSymbolAddress((void**)&bufA, g_bufA);
    cudaGetSymbolAddress((void**)&bufB, g_bufB);
    cudaGetSymbolAddress((void**)&stats, g_stats);
    cudaGetSymbolAddress((void**)&scalep, g_scale);
    cudaGetSymbolAddress((void**)&shiftp, g_shift);
    cudaGetSymbolAddress((void**)&xg, g_xg);
    cudaGetSymbolAddress((void**)&m1, g_m1);
    cudaGetSymbolAddress((void**)&m2, g_m2);
    cudaGetSymbolAddress((void**)&rowptr, g_rowptr);
    cudaGetSymbolAddress((void**)&cursor, g_cursor);

    cudaFuncSetAttribute(gemm128_kernel, cudaFuncAttributeMaxDynamicSharedMemorySize, 98304);

    const int WB = (NN * 32 + 255) / 256;   // warp-per-node grids
    const int EB = (EE + 255) / 256;
    const int GB = (NN + 63) / 64;

    // ---- CSR build (once per launch; reused for all 5 layers) ----
    cudaMemsetAsync(rowptr, 0, (NN + 1) * sizeof(int));
    hist_kernel<<<EB, 256>>>(edst);
    scan_kernel<<<1, 1024>>>(rowptr, NN + 1);
    cudaMemsetAsync(cursor, 0, NN * sizeof(int));
    fill_kernel<<<EB, 256>>>(esrc, edst);

    // ---- layer 0 ----
    agg0_kernel<<<WB, 256>>>(h);
    cudaMemsetAsync(stats, 0, 1024 * sizeof(float));
    gemm128_kernel<<<GB, 256, 98304>>>(bufA, W1, b1, 2.f, NN, 78, bufB, stats);
    finalize_kernel<<<1, 128>>>(stats, g1_gamma, g1_beta, 1.f / NN, 128, scalep, shiftp);

    // ---- layers 1..4 ----
    for (int l = 0; l < 4; ++l) {
        agg_kernel<<<WB, 256>>>(bufB, bufA, scalep, shiftp);
        cudaMemsetAsync(stats, 0, 1024 * sizeof(float));
        gemm128_kernel<<<GB, 256, 98304>>>(bufA, Wg + (size_t)l * 128 * 128, bg + l * 128,
                                           2.f, NN, 128, bufB, stats);
        finalize_kernel<<<1, 128>>>(stats, gg + l * 128, gb + l * 128, 1.f / NN, 128,
                                    scalep, shiftp);
    }

    // ---- graph sum readout ----
    cudaMemsetAsync(xg, 0, GG * 128 * sizeof(float));
    readout_kernel<<<WB, 256>>>(bufB, gid, scalep, shiftp);

    // ---- MLP head ----
    cudaMemsetAsync(stats, 0, 1024 * sizeof(float));
    gemm_small_kernel<<<dim3(512 / 32, GG / 8), 256>>>(xg, fc1_W, fc1_b, GG, 128, 512, m1, stats);
    finalize_kernel<<<1, 512>>>(stats, bn1_g, bn1_b, 1.f / GG, 512, scalep, shiftp);
    norm_relu_kernel<<<(GG * 512 + 255) / 256, 256>>>(m1, scalep, shiftp, GG * 512, 512);

    cudaMemsetAsync(stats, 0, 1024 * sizeof(float));
    gemm_small_kernel<<<dim3(256 / 32, GG / 8), 256>>>(m1, lin_W, lin_b, GG, 512, 256, m2, stats);
    finalize_kernel<<<1, 256>>>(stats, lbn_g, lbn_b, 1.f / GG, 256, scalep, shiftp);
    norm_relu_kernel<<<(GG * 256 + 255) / 256, 256>>>(m2, scalep, shiftp, GG * 256, 256);

    fc2_kernel<<<dim3(7, GG / 8), 256>>>(m2, fc2_W, fc2_b, out);
}